// round 13
// baseline (speedup 1.0000x reference)
#include <cuda_runtime.h>
#include <cuda_bf16.h>
#include <cstdint>

// MySoftBCELoss: B=1048576 rows, C=32 classes, fp32 -> scalar.
// No-smem streamer: 1 warp = 4 rows (8 lanes/row, 4 classes/lane).
// Fully coalesced LDG.128, width-8 butterfly argmax, MUFU softplus.
// Light path (label!=0, 31/32): 2 softplus. Heavy path (label==0): full row BCE.

#define BLOCK 256
#define WARPS_CTA (BLOCK / 32)               // 8
#define NCTAS (148 * 8)                      // 1184
#define TOTAL_WARPS (NCTAS * WARPS_CTA)      // 9472
#define NCLS 32
#define ROWS_TOTAL 1048576
#define GROUPS (ROWS_TOTAL / 4)              // 262144 groups of 4 rows
#define GSTRIDE (TOTAL_WARPS * 2)            // 18944 (2 groups per iter)

#define LOG_EPS   (-16.11809565095832f)      // log(1e-7)
#define LOG_1MEPS (-1.0000000494736474e-07f) // log(1 - 1e-7)

__device__ float g_partials[NCTAS];
__device__ int   g_count = 0;

__device__ __forceinline__ float softplus_f(float x) {
    return fmaxf(x, 0.0f) + __logf(1.0f + __expf(-fabsf(x)));
}
__device__ __forceinline__ float clamp_log(float v) {
    return fminf(fmaxf(v, LOG_EPS), LOG_1MEPS);
}

// Process one 4-row group held in (lv, tv) across the warp; returns the
// per-lane loss contribution (nonzero only on segment-leader lanes).
__device__ __forceinline__ float group_loss(float4 lv, float4 tv,
                                            int sub, unsigned m)
{
    // local max of my 4 targets
    float tl = fmaxf(fmaxf(tv.x, tv.y), fmaxf(tv.z, tv.w));

    // segment (8-lane) max
    float tm = tl;
    tm = fmaxf(tm, __shfl_xor_sync(m, tm, 1, 8));
    tm = fmaxf(tm, __shfl_xor_sync(m, tm, 2, 8));
    tm = fmaxf(tm, __shfl_xor_sync(m, tm, 4, 8));

    // first-occurrence class index where t == tm (exact jnp.argmax semantics)
    int cbase = sub * 4;
    int cc = 1000;
    if (tv.w == tm) cc = cbase + 3;
    if (tv.z == tm) cc = cbase + 2;
    if (tv.y == tm) cc = cbase + 1;
    if (tv.x == tm) cc = cbase + 0;
    cc = min(cc, __shfl_xor_sync(m, cc, 1, 8));
    cc = min(cc, __shfl_xor_sync(m, cc, 2, 8));
    cc = min(cc, __shfl_xor_sync(m, cc, 4, 8));
    const int cmax = cc;

    // broadcast x0 (class 0 = segment lane 0, component x)
    float x0 = __shfl_sync(m, lv.x, 0, 8);

    // xlab = logits[row, cmax]: source lane = cmax>>2, component = cmax&3
    int ks = cmax & 3;
    float a0 = (ks & 1) ? lv.y : lv.x;
    float b0 = (ks & 1) ? lv.w : lv.z;
    float xsel = (ks & 2) ? b0 : a0;
    float xlab = __shfl_sync(m, xsel, cmax >> 2, 8);

    // heavy-path lane mask (uniform within each 8-lane segment)
    unsigned hm = __ballot_sync(m, cmax == 0);

    float loss;
    if (cmax != 0) {
        // light path: 2 softplus
        float lp_lab = clamp_log(xlab - softplus_f(xlab));
        float l1p0   = clamp_log(-softplus_f(x0));
        loss = fmaf(tm, lp_lab, l1p0);           // NEG_WEIGHT = 1
    } else {
        // heavy path: full-row soft BCE mean
        float xs[4] = {lv.x, lv.y, lv.z, lv.w};
        float ts[4] = {tv.x, tv.y, tv.z, tv.w};
        float p = 0.0f;
        #pragma unroll
        for (int k = 0; k < 4; k++) {
            float L   = softplus_f(xs[k]);
            float lp  = clamp_log(xs[k] - L);
            float l1p = clamp_log(-L);
            p += fmaf(ts[k], lp - l1p, l1p);
        }
        p += __shfl_xor_sync(hm, p, 1, 8);
        p += __shfl_xor_sync(hm, p, 2, 8);
        p += __shfl_xor_sync(hm, p, 4, 8);
        loss = p * (1.0f / (float)NCLS);
    }
    return (sub == 0) ? loss : 0.0f;
}

__global__ void __launch_bounds__(BLOCK) softbce_stream(
    const float4* __restrict__ logits4,
    const float4* __restrict__ target4,
    float* __restrict__ out)
{
    const int tid  = threadIdx.x;
    const int wid  = tid >> 5;
    const int lane = tid & 31;
    const int sub  = lane & 7;                 // position within row
    const unsigned m = 0xFFFFFFFFu;

    const int gwarp = blockIdx.x * WARPS_CTA + wid;   // 0..9471

    float acc = 0.0f;

    // Grid-stride over group pairs; GROUPS is even and strides are even,
    // so both groups of each pair are always in range.
    for (int g = gwarp * 2; g < GROUPS; g += GSTRIDE) {
        const size_t i0 = (size_t)g * 32 + lane;
        // front-batched loads (MLP = 4)
        float4 la = __ldg(logits4 + i0);
        float4 ta = __ldg(target4 + i0);
        float4 lb = __ldg(logits4 + i0 + 32);
        float4 tb = __ldg(target4 + i0 + 32);

        acc += group_loss(la, ta, sub, m);
        acc += group_loss(lb, tb, sub, m);
    }

    // ---- warp reduce ----
    #pragma unroll
    for (int o = 16; o > 0; o >>= 1)
        acc += __shfl_xor_sync(m, acc, o);

    __shared__ float warp_sums[WARPS_CTA];
    __shared__ bool  is_last;
    if (lane == 0) warp_sums[wid] = acc;
    __syncthreads();

    if (tid == 0) {
        float b = warp_sums[0];
        #pragma unroll
        for (int w = 1; w < WARPS_CTA; w++) b += warp_sums[w];
        g_partials[blockIdx.x] = b;
        __threadfence();
        int prev = atomicAdd(&g_count, 1);
        is_last = (prev == NCTAS - 1);
    }
    __syncthreads();

    // ---- last CTA: deterministic final reduce ----
    if (is_last) {
        float s = 0.0f;
        for (int i = tid; i < NCTAS; i += BLOCK)
            s += g_partials[i];
        #pragma unroll
        for (int o = 16; o > 0; o >>= 1)
            s += __shfl_xor_sync(m, s, o);
        if ((tid & 31) == 0) warp_sums[tid >> 5] = s;
        __syncthreads();
        if (tid == 0) {
            float total = warp_sums[0];
            #pragma unroll
            for (int w = 1; w < WARPS_CTA; w++) total += warp_sums[w];
            out[0] = -total * (1.0f / (float)ROWS_TOTAL);
            g_count = 0;   // reset for next graph replay
        }
    }
}

extern "C" void kernel_launch(void* const* d_in, const int* in_sizes, int n_in,
                              void* d_out, int out_size)
{
    const float4* logits = (const float4*)d_in[0];
    const float4* target = (const float4*)d_in[1];
    float* out = (float*)d_out;

    softbce_stream<<<NCTAS, BLOCK>>>(logits, target, out);
}

// round 14
// speedup vs baseline: 1.0137x; 1.0137x over previous
#include <cuda_runtime.h>
#include <cuda_bf16.h>
#include <cstdint>

// MySoftBCELoss: B=1048576 rows, C=32 classes, fp32 -> scalar.
// No-smem streamer: 1 warp = 4 rows (8 lanes/row, 4 classes/lane).
// Register software-pipeline (prefetch next iter's loads before compute),
// packed 64-bit argmax key (one 3-level shuffle chain), MUFU softplus.

#define BLOCK 256
#define WARPS_CTA (BLOCK / 32)               // 8
#define NCTAS (148 * 8)                      // 1184
#define TOTAL_WARPS (NCTAS * WARPS_CTA)      // 9472
#define NCLS 32
#define ROWS_TOTAL 1048576
#define GROUPS (ROWS_TOTAL / 4)              // 262144 groups of 4 rows
#define GSTRIDE (TOTAL_WARPS * 2)            // 18944 (2 groups per iter)

#define LOG_EPS   (-16.11809565095832f)      // log(1e-7)
#define LOG_1MEPS (-1.0000000494736474e-07f) // log(1 - 1e-7)

__device__ float g_partials[NCTAS];
__device__ int   g_count = 0;

__device__ __forceinline__ float softplus_f(float x) {
    return fmaxf(x, 0.0f) + __logf(1.0f + __expf(-fabsf(x)));
}
__device__ __forceinline__ float clamp_log(float v) {
    return fminf(fmaxf(v, LOG_EPS), LOG_1MEPS);
}

// One 4-row group; returns per-lane contribution (segment leaders only).
__device__ __forceinline__ float group_loss(float4 lv, float4 tv,
                                            int sub, unsigned m)
{
    // Packed argmax key: (t_bits << 32) | (31 - c). t >= 0 so float bits
    // are order-isomorphic; ties pick larger (31-c) => smaller c (first occ).
    const int cbase = sub * 4;
    unsigned long long k0 = ((unsigned long long)(unsigned)__float_as_int(tv.x) << 32) | (unsigned)(31 - (cbase + 0));
    unsigned long long k1 = ((unsigned long long)(unsigned)__float_as_int(tv.y) << 32) | (unsigned)(31 - (cbase + 1));
    unsigned long long k2 = ((unsigned long long)(unsigned)__float_as_int(tv.z) << 32) | (unsigned)(31 - (cbase + 2));
    unsigned long long k3 = ((unsigned long long)(unsigned)__float_as_int(tv.w) << 32) | (unsigned)(31 - (cbase + 3));
    unsigned long long key = max(max(k0, k1), max(k2, k3));

    // single 3-level segment (width=8) max chain
    key = max(key, __shfl_xor_sync(m, key, 1, 8));
    key = max(key, __shfl_xor_sync(m, key, 2, 8));
    key = max(key, __shfl_xor_sync(m, key, 4, 8));

    const float tmax = __int_as_float((int)(key >> 32));
    const int   cmax = 31 - (int)(key & 0xFFu);

    // x0 (class 0 = segment lane 0, component x)
    float x0 = __shfl_sync(m, lv.x, 0, 8);

    // xlab = logits[row, cmax]: source lane = cmax>>2, component = cmax&3
    int ks = cmax & 3;
    float a0 = (ks & 1) ? lv.y : lv.x;
    float b0 = (ks & 1) ? lv.w : lv.z;
    float xsel = (ks & 2) ? b0 : a0;
    float xlab = __shfl_sync(m, xsel, cmax >> 2, 8);

    // heavy-path lane mask (uniform within each 8-lane segment)
    unsigned hm = __ballot_sync(m, cmax == 0);

    float loss;
    if (cmax != 0) {
        // light path: 2 softplus
        float lp_lab = clamp_log(xlab - softplus_f(xlab));
        float l1p0   = clamp_log(-softplus_f(x0));
        loss = fmaf(tmax, lp_lab, l1p0);          // NEG_WEIGHT = 1
    } else {
        // heavy path: full-row soft BCE mean
        float xs[4] = {lv.x, lv.y, lv.z, lv.w};
        float ts[4] = {tv.x, tv.y, tv.z, tv.w};
        float p = 0.0f;
        #pragma unroll
        for (int k = 0; k < 4; k++) {
            float L   = softplus_f(xs[k]);
            float lp  = clamp_log(xs[k] - L);
            float l1p = clamp_log(-L);
            p += fmaf(ts[k], lp - l1p, l1p);
        }
        p += __shfl_xor_sync(hm, p, 1, 8);
        p += __shfl_xor_sync(hm, p, 2, 8);
        p += __shfl_xor_sync(hm, p, 4, 8);
        loss = p * (1.0f / (float)NCLS);
    }
    return (sub == 0) ? loss : 0.0f;
}

__global__ void __launch_bounds__(BLOCK) softbce_pipe(
    const float4* __restrict__ logits4,
    const float4* __restrict__ target4,
    float* __restrict__ out)
{
    const int tid  = threadIdx.x;
    const int wid  = tid >> 5;
    const int lane = tid & 31;
    const int sub  = lane & 7;
    const unsigned m = 0xFFFFFFFFu;

    const int gwarp = blockIdx.x * WARPS_CTA + wid;   // 0..9471

    float acc = 0.0f;

    // ---- register software pipeline over group pairs ----
    int g = gwarp * 2;
    float4 la, ta, lb, tb;
    if (g < GROUPS) {
        const size_t i0 = (size_t)g * 32 + lane;
        la = __ldg(logits4 + i0);
        ta = __ldg(target4 + i0);
        lb = __ldg(logits4 + i0 + 32);
        tb = __ldg(target4 + i0 + 32);
    }
    for (; g < GROUPS; g += GSTRIDE) {
        // prefetch next pair (reload current when none: deterministic, rare)
        int gn = g + GSTRIDE;
        const size_t i1 = (size_t)((gn < GROUPS) ? gn : g) * 32 + lane;
        float4 la2 = __ldg(logits4 + i1);
        float4 ta2 = __ldg(target4 + i1);
        float4 lb2 = __ldg(logits4 + i1 + 32);
        float4 tb2 = __ldg(target4 + i1 + 32);

        // process current pair while next loads are in flight
        acc += group_loss(la, ta, sub, m);
        acc += group_loss(lb, tb, sub, m);

        la = la2; ta = ta2; lb = lb2; tb = tb2;
    }

    // ---- warp reduce ----
    #pragma unroll
    for (int o = 16; o > 0; o >>= 1)
        acc += __shfl_xor_sync(m, acc, o);

    __shared__ float warp_sums[WARPS_CTA];
    __shared__ bool  is_last;
    if (lane == 0) warp_sums[wid] = acc;
    __syncthreads();

    if (tid == 0) {
        float b = warp_sums[0];
        #pragma unroll
        for (int w = 1; w < WARPS_CTA; w++) b += warp_sums[w];
        g_partials[blockIdx.x] = b;
        __threadfence();
        int prev = atomicAdd(&g_count, 1);
        is_last = (prev == NCTAS - 1);
    }
    __syncthreads();

    // ---- last CTA: deterministic final reduce ----
    if (is_last) {
        float s = 0.0f;
        for (int i = tid; i < NCTAS; i += BLOCK)
            s += g_partials[i];
        #pragma unroll
        for (int o = 16; o > 0; o >>= 1)
            s += __shfl_xor_sync(m, s, o);
        if ((tid & 31) == 0) warp_sums[tid >> 5] = s;
        __syncthreads();
        if (tid == 0) {
            float total = warp_sums[0];
            #pragma unroll
            for (int w = 1; w < WARPS_CTA; w++) total += warp_sums[w];
            out[0] = -total * (1.0f / (float)ROWS_TOTAL);
            g_count = 0;   // reset for next graph replay
        }
    }
}

extern "C" void kernel_launch(void* const* d_in, const int* in_sizes, int n_in,
                              void* d_out, int out_size)
{
    const float4* logits = (const float4*)d_in[0];
    const float4* target = (const float4*)d_in[1];
    float* out = (float*)d_out;

    softbce_pipe<<<NCTAS, BLOCK>>>(logits, target, out);
}

// round 15
// speedup vs baseline: 1.0904x; 1.0757x over previous
#include <cuda_runtime.h>
#include <cuda_bf16.h>
#include <cstdint>

// MySoftBCELoss: B=1048576 rows, C=32 classes, fp32 -> scalar.
// Deferred sector-gather pipeline:
//   - target streamed fully via warp-autonomous cp.async tiles (32 rows/warp)
//   - per row: argmax scan in smem (per-lane, no shuffles)
//   - light rows (label!=0): two 16B cp.async gathers of logits sectors,
//     consumed one iteration later (latency hidden)
//   - heavy rows (label==0, ~3%): immediate per-lane full-row BCE via __ldg
// softplus via MUFU; lp/l1p clamped to [log(eps), log(1-eps)].

#define BLOCK 128
#define WARPS (BLOCK / 32)                   // 4
#define TILE_ROWS 32                         // 1 lane = 1 row
#define NCLS 32
#define ROWS_TOTAL 1048576
#define NTILES (ROWS_TOTAL / TILE_ROWS)      // 32768
#define NCTAS (148 * 5)                      // 740 persistent CTAs (45KB smem)
#define TOTAL_WARPS (NCTAS * WARPS)          // 2960
#define PITCH4 9                             // float4 per smem row (144 B)
#define T4_PER_TILE (TILE_ROWS * NCLS / 4)   // 256 float4 per target tile
#define WBUF4 (TILE_ROWS * PITCH4)           // 288 float4 per target buf

#define LOG_EPS   (-16.11809565095832f)      // log(1e-7)
#define LOG_1MEPS (-1.0000000494736474e-07f) // log(1 - 1e-7)

__device__ float g_partials[NCTAS];
__device__ int   g_count = 0;

__device__ __forceinline__ void cp_async16(unsigned int saddr, const void* gptr) {
    asm volatile("cp.async.cg.shared.global [%0], [%1], 16;\n"
                 :: "r"(saddr), "l"(gptr));
}
__device__ __forceinline__ void cp_commit() { asm volatile("cp.async.commit_group;\n"); }
__device__ __forceinline__ void cp_wait1()  { asm volatile("cp.async.wait_group 1;\n" ::: "memory"); }
__device__ __forceinline__ void cp_wait0()  { asm volatile("cp.async.wait_group 0;\n" ::: "memory"); }

__device__ __forceinline__ float softplus_f(float x) {
    return fmaxf(x, 0.0f) + __logf(1.0f + __expf(-fabsf(x)));
}
__device__ __forceinline__ float clamp_log(float v) {
    return fminf(fmaxf(v, LOG_EPS), LOG_1MEPS);
}

__global__ void __launch_bounds__(BLOCK) softbce_sector(
    const float*  __restrict__ logits,
    const float4* __restrict__ target4,
    float* __restrict__ out)
{
    // per-warp double-buffered target tiles + gather slots
    __shared__ float4 tbuf[WARPS][2][WBUF4];        // 4*2*288*16 = 36864 B
    __shared__ float  gbuf[WARPS][2][TILE_ROWS][8]; // 4*2*32*8*4  =  8192 B
    __shared__ float  warp_sums[WARPS];
    __shared__ bool   is_last;

    const int tid  = threadIdx.x;
    const int wid  = tid >> 5;
    const int lane = tid & 31;
    const unsigned m = 0xFFFFFFFFu;

    const int gwarp   = blockIdx.x * WARPS + wid;               // 0..2959
    const int n_tiles = (gwarp < NTILES)
                        ? ((NTILES - 1 - gwarp) / TOTAL_WARPS + 1) : 0;  // 11 or 12

    const unsigned int tb_base =
        (unsigned int)__cvta_generic_to_shared(&tbuf[wid][0][0]);
    const unsigned int tb_stride = (unsigned int)(WBUF4 * 16);
    const unsigned int gb_base =
        (unsigned int)__cvta_generic_to_shared(&gbuf[wid][0][0][0]);
    const unsigned int gb_stride = (unsigned int)(TILE_ROWS * 8 * 4);  // per buf

    // target staging offsets: fi = lane + it*32; srow = fi>>3, q = fi&7
    unsigned int soff[8];
    #pragma unroll
    for (int it = 0; it < 8; it++) {
        int fi   = lane + it * 32;
        soff[it] = (unsigned int)(((fi >> 3) * PITCH4 + (fi & 7)) * 16);
    }

    float acc = 0.0f;

    // deferred-light state (carried one iteration)
    float tmax_p = 0.0f;
    int   cmax_p = 0;      // 0 => nothing deferred (heavy handled immediately)

    // ---- prologue: stage target tile gwarp into tbuf 0 ----
    if (n_tiles > 0) {
        const size_t gbase = (size_t)gwarp * T4_PER_TILE;
        #pragma unroll
        for (int it = 0; it < 8; it++)
            cp_async16(tb_base + soff[it], target4 + gbase + lane + it * 32);
    }
    cp_commit();

    int tile = gwarp;
    for (int k = 0; k < n_tiles; k++, tile += TOTAL_WARPS) {
        const int buf = k & 1;

        // ---- stage target tile k+1 (or commit empty to keep ring aligned) ----
        if (k + 1 < n_tiles) {
            const size_t gbase = (size_t)(tile + TOTAL_WARPS) * T4_PER_TILE;
            const unsigned int bb = tb_base + (unsigned int)(buf ^ 1) * tb_stride;
            #pragma unroll
            for (int it = 0; it < 8; it++)
                cp_async16(bb + soff[it], target4 + gbase + lane + it * 32);
        }
        cp_commit();
        cp_wait1();     // FIFO: everything except newest group is complete
                        // => target tile k staged AND gather k-1 landed
        __syncwarp(m);

        // ---- scan my row's target for argmax (first occurrence) ----
        const float4* trow = &tbuf[wid][buf][lane * PITCH4];
        float tmax = -1.0f;
        int   cmax = 0;
        #pragma unroll
        for (int q = 0; q < 8; q++) {
            float4 tv = trow[q];
            if (tv.x > tmax) { tmax = tv.x; cmax = q * 4 + 0; }
            if (tv.y > tmax) { tmax = tv.y; cmax = q * 4 + 1; }
            if (tv.z > tmax) { tmax = tv.z; cmax = q * 4 + 2; }
            if (tv.w > tmax) { tmax = tv.w; cmax = q * 4 + 3; }
        }

        const size_t row_g  = (size_t)tile * TILE_ROWS + lane;
        const float* lrowg  = logits + row_g * NCLS;

        if (cmax == 0) {
            // ---- heavy path (rare): immediate full-row BCE ----
            const float4* lrow4 = (const float4*)lrowg;
            float sum0 = 0.0f;
            #pragma unroll
            for (int q = 0; q < 8; q++) {
                float4 lv = __ldg(lrow4 + q);
                float4 tv = trow[q];
                float xs[4] = {lv.x, lv.y, lv.z, lv.w};
                float ts[4] = {tv.x, tv.y, tv.z, tv.w};
                #pragma unroll
                for (int kk = 0; kk < 4; kk++) {
                    float L   = softplus_f(xs[kk]);
                    float lp  = clamp_log(xs[kk] - L);
                    float l1p = clamp_log(-L);
                    sum0 += fmaf(ts[kk], lp - l1p, l1p);
                }
            }
            acc += sum0 * (1.0f / (float)NCLS);
        } else {
            // ---- light path: issue two 16B sector gathers for this row ----
            const unsigned int gslot = gb_base + (unsigned int)buf * gb_stride
                                     + (unsigned int)(lane * 32);   // 8 floats
            cp_async16(gslot,     lrowg);                       // classes 0..3
            cp_async16(gslot + 16, lrowg + (cmax & ~3));        // chunk w/ cmax
        }
        cp_commit();    // gather group for tile k (possibly empty on this lane? no:
                        // commit is warp-level; lanes w/o gathers contribute none)

        // ---- consume tile k-1's deferred light loss ----
        if (k > 0 && cmax_p != 0) {
            const float* gs = &gbuf[wid][buf ^ 1][lane][0];
            float x0   = gs[0];
            float xlab = gs[4 + (cmax_p & 3)];
            float lp_lab = clamp_log(xlab - softplus_f(xlab));
            float l1p0   = clamp_log(-softplus_f(x0));
            acc += fmaf(tmax_p, lp_lab, l1p0);      // NEG_WEIGHT = 1
        }

        tmax_p = tmax;
        cmax_p = cmax;
        __syncwarp(m);
    }

    // ---- epilogue: last tile's deferred light loss ----
    cp_wait0();
    __syncwarp(m);
    if (n_tiles > 0 && cmax_p != 0) {
        const float* gs = &gbuf[wid][(n_tiles - 1) & 1][lane][0];
        float x0   = gs[0];
        float xlab = gs[4 + (cmax_p & 3)];
        float lp_lab = clamp_log(xlab - softplus_f(xlab));
        float l1p0   = clamp_log(-softplus_f(x0));
        acc += fmaf(tmax_p, lp_lab, l1p0);
    }

    // ---- warp reduce ----
    #pragma unroll
    for (int o = 16; o > 0; o >>= 1)
        acc += __shfl_xor_sync(m, acc, o);
    if (lane == 0) warp_sums[wid] = acc;
    __syncthreads();

    if (tid == 0) {
        g_partials[blockIdx.x] = warp_sums[0] + warp_sums[1]
                               + warp_sums[2] + warp_sums[3];
        __threadfence();
        int prev = atomicAdd(&g_count, 1);
        is_last = (prev == NCTAS - 1);
    }
    __syncthreads();

    // ---- last CTA: deterministic final reduce ----
    if (is_last) {
        float s = 0.0f;
        for (int i = tid; i < NCTAS; i += BLOCK)
            s += g_partials[i];
        #pragma unroll
        for (int o = 16; o > 0; o >>= 1)
            s += __shfl_xor_sync(m, s, o);
        if ((tid & 31) == 0) warp_sums[tid >> 5] = s;
        __syncthreads();
        if (tid == 0) {
            out[0] = -(warp_sums[0] + warp_sums[1] + warp_sums[2] + warp_sums[3])
                     * (1.0f / (float)ROWS_TOTAL);
            g_count = 0;   // reset for next graph replay
        }
    }
}

extern "C" void kernel_launch(void* const* d_in, const int* in_sizes, int n_in,
                              void* d_out, int out_size)
{
    const float*  logits = (const float*)d_in[0];
    const float4* target = (const float4*)d_in[1];
    float* out = (float*)d_out;

    softbce_sector<<<NCTAS, BLOCK>>>(logits, target, out);
}